// round 1
// baseline (speedup 1.0000x reference)
#include <cuda_runtime.h>
#include <stdint.h>
#include <math.h>

// Problem constants
#define T_TOK 1024
#define H_DIM 2048
#define F_DIM 4096
#define E_EXP 8
#define EFDIM ((size_t)E_EXP * (size_t)F_DIM)  // 32768

// Scratch (device globals: allocation-free per harness rules)
__device__ float g_weights[T_TOK * E_EXP];                       // gate weights (T,E)
__device__ float g_A[(size_t)T_TOK * E_EXP * F_DIM];             // A' = weighted swiglu acts (T, E*F), 128MB
__device__ float g_part[2 * T_TOK * H_DIM];                      // K-split partials for final GEMM

__device__ __forceinline__ uint32_t f2tf(float f) {
    uint32_t u;
    asm("cvt.rna.tf32.f32 %0, %1;" : "=r"(u) : "f"(f));
    return u;
}

__device__ __forceinline__ float silu_f(float v) { return v / (1.0f + expf(-v)); }

__device__ __forceinline__ void mma_tf32(float& c0, float& c1, float& c2, float& c3,
                                         uint32_t a0, uint32_t a1, uint32_t a2, uint32_t a3,
                                         uint32_t b0, uint32_t b1) {
    asm volatile(
        "mma.sync.aligned.m16n8k8.row.col.f32.tf32.tf32.f32 "
        "{%0,%1,%2,%3}, {%4,%5,%6,%7}, {%8,%9}, {%0,%1,%2,%3};\n"
        : "+f"(c0), "+f"(c1), "+f"(c2), "+f"(c3)
        : "r"(a0), "r"(a1), "r"(a2), "r"(a3), "r"(b0), "r"(b1));
}

// ---------------------------------------------------------------------------
// Gate: logits = x @ w_gate, then emulated top-2 -> per-(token,expert) weight
// One warp per token.
// ---------------------------------------------------------------------------
__global__ void gate_kernel(const float* __restrict__ x, const float* __restrict__ wg) {
    int warps_per_block = blockDim.x >> 5;
    int t = blockIdx.x * warps_per_block + (threadIdx.x >> 5);
    int lane = threadIdx.x & 31;
    if (t >= T_TOK) return;

    const float* xr = x + (size_t)t * H_DIM;
    float acc[E_EXP];
#pragma unroll
    for (int e = 0; e < E_EXP; e++) acc[e] = 0.0f;

    for (int h = lane; h < H_DIM; h += 32) {
        float xv = xr[h];
        const float* wrow = wg + (size_t)h * E_EXP;
#pragma unroll
        for (int e = 0; e < E_EXP; e++) acc[e] += xv * wrow[e];
    }
#pragma unroll
    for (int e = 0; e < E_EXP; e++) {
#pragma unroll
        for (int o = 16; o > 0; o >>= 1) acc[e] += __shfl_xor_sync(0xffffffffu, acc[e], o);
    }
    if (lane == 0) {
        int i0 = 0;
        float v0 = acc[0];
#pragma unroll
        for (int e = 1; e < E_EXP; e++) {
            if (acc[e] > v0) { v0 = acc[e]; i0 = e; }
        }
        int i1 = -1;
        float v1 = -INFINITY;
#pragma unroll
        for (int e = 0; e < E_EXP; e++) {
            if (e != i0 && acc[e] > v1) { v1 = acc[e]; i1 = e; }
        }
        float w0 = 1.0f / (1.0f + expf(v1 - v0));  // sigmoid(v0 - v1)
#pragma unroll
        for (int e = 0; e < E_EXP; e++) {
            float w = (e == i0) ? w0 : ((e == i1) ? (1.0f - w0) : 0.0f);
            g_weights[t * E_EXP + e] = w;
        }
    }
}

// ---------------------------------------------------------------------------
// tf32 GEMM, 128x128x32 tile, 256 threads (8 warps as 4(M) x 2(N)),
// warp tile 32x64 via 2x8 m16n8k8 mma tiles.
//
// mode 0: C = x @ w1[e];       epilogue: g_A[t, e*F + n] = silu(C)
// mode 1: C = x @ w3[e];       epilogue: g_A[t, e*F + n] *= C * weight[t,e]
// mode 2: C = g_A @ w2 (K-slice z); epilogue: g_part[z][t, n] = C
// ---------------------------------------------------------------------------
__global__ __launch_bounds__(256, 2) void gemm_kernel(const float* __restrict__ Ap,
                                                      const float* __restrict__ Bp,
                                                      int K, int lda, int ldb, int mode) {
    __shared__ uint32_t As[128][36];   // padded: conflict-free frag reads
    __shared__ uint32_t Bs[32][136];

    const int tid = threadIdx.x;
    const int warp = tid >> 5;
    const int lane = tid & 31;
    const int wm = warp & 3;       // 0..3 (M)
    const int wn = warp >> 2;      // 0..1 (N)
    const int g = lane >> 2;       // groupID 0..7
    const int tg = lane & 3;       // threadID in group 0..3

    const int bm = blockIdx.y * 128;
    const int bn = blockIdx.x * 128;
    const int z = blockIdx.z;      // expert (mode 0/1) or K-slice (mode 2)

    const float* Abase;
    const float* Bbase;
    if (mode <= 1) {
        Abase = Ap;                                             // x, lda = H
        Bbase = Bp + (size_t)z * H_DIM * F_DIM;                 // w1/w3 expert slab
    } else {
        size_t koff = (size_t)z * (size_t)K;                    // K-slice offset
        Abase = g_A + koff;                                     // lda = E*F
        Bbase = Bp + koff * (size_t)ldb;                        // w2 rows
    }

    float c[2][8][4];
#pragma unroll
    for (int mi = 0; mi < 2; mi++)
#pragma unroll
        for (int ni = 0; ni < 8; ni++)
#pragma unroll
            for (int q = 0; q < 4; q++) c[mi][ni][q] = 0.0f;

    for (int k0 = 0; k0 < K; k0 += 32) {
        // Stage A tile (128 x 32): 1024 float4 slots, 4 per thread
#pragma unroll
        for (int i = 0; i < 4; i++) {
            int slot = tid + i * 256;
            int r = slot >> 3;
            int c4 = (slot & 7) << 2;
            float4 v = *reinterpret_cast<const float4*>(Abase + (size_t)(bm + r) * lda + k0 + c4);
            uint4 u = make_uint4(f2tf(v.x), f2tf(v.y), f2tf(v.z), f2tf(v.w));
            *reinterpret_cast<uint4*>(&As[r][c4]) = u;  // row stride 144B -> 16B aligned
        }
        // Stage B tile (32 x 128): 1024 float4 slots, 4 per thread
#pragma unroll
        for (int i = 0; i < 4; i++) {
            int slot = tid + i * 256;
            int r = slot >> 5;
            int c4 = (slot & 31) << 2;
            float4 v = *reinterpret_cast<const float4*>(Bbase + (size_t)(k0 + r) * ldb + bn + c4);
            uint4 u = make_uint4(f2tf(v.x), f2tf(v.y), f2tf(v.z), f2tf(v.w));
            *reinterpret_cast<uint4*>(&Bs[r][c4]) = u;  // row stride 544B -> 16B aligned
        }
        __syncthreads();

#pragma unroll
        for (int ks = 0; ks < 4; ks++) {
            const int kk = ks * 8;
            uint32_t a[2][4];
            uint32_t b[8][2];
#pragma unroll
            for (int mi = 0; mi < 2; mi++) {
                int r0 = wm * 32 + mi * 16;
                a[mi][0] = As[r0 + g][kk + tg];
                a[mi][1] = As[r0 + 8 + g][kk + tg];
                a[mi][2] = As[r0 + g][kk + tg + 4];
                a[mi][3] = As[r0 + 8 + g][kk + tg + 4];
            }
#pragma unroll
            for (int ni = 0; ni < 8; ni++) {
                int col = wn * 64 + ni * 8 + g;
                b[ni][0] = Bs[kk + tg][col];
                b[ni][1] = Bs[kk + tg + 4][col];
            }
#pragma unroll
            for (int mi = 0; mi < 2; mi++)
#pragma unroll
                for (int ni = 0; ni < 8; ni++)
                    mma_tf32(c[mi][ni][0], c[mi][ni][1], c[mi][ni][2], c[mi][ni][3],
                             a[mi][0], a[mi][1], a[mi][2], a[mi][3],
                             b[ni][0], b[ni][1]);
        }
        __syncthreads();
    }

    // Epilogue. Element map: c0->(r0,cl), c1->(r0,cl+1), c2->(r0+8,cl), c3->(r0+8,cl+1)
    const int r_base = bm + wm * 32;
    const int c_base = bn + wn * 64;

    if (mode == 0) {
#pragma unroll
        for (int mi = 0; mi < 2; mi++) {
            int r0 = r_base + mi * 16 + g;
            size_t o0 = (size_t)r0 * EFDIM + (size_t)z * F_DIM;
            size_t o1 = (size_t)(r0 + 8) * EFDIM + (size_t)z * F_DIM;
#pragma unroll
            for (int ni = 0; ni < 8; ni++) {
                int cl = c_base + ni * 8 + 2 * tg;
                float2 v0 = make_float2(silu_f(c[mi][ni][0]), silu_f(c[mi][ni][1]));
                float2 v1 = make_float2(silu_f(c[mi][ni][2]), silu_f(c[mi][ni][3]));
                *reinterpret_cast<float2*>(g_A + o0 + cl) = v0;
                *reinterpret_cast<float2*>(g_A + o1 + cl) = v1;
            }
        }
    } else if (mode == 1) {
#pragma unroll
        for (int mi = 0; mi < 2; mi++) {
            int r0 = r_base + mi * 16 + g;
            float wa = g_weights[r0 * E_EXP + z];
            float wb = g_weights[(r0 + 8) * E_EXP + z];
            size_t o0 = (size_t)r0 * EFDIM + (size_t)z * F_DIM;
            size_t o1 = (size_t)(r0 + 8) * EFDIM + (size_t)z * F_DIM;
#pragma unroll
            for (int ni = 0; ni < 8; ni++) {
                int cl = c_base + ni * 8 + 2 * tg;
                float2 p0 = *reinterpret_cast<const float2*>(g_A + o0 + cl);
                float2 p1 = *reinterpret_cast<const float2*>(g_A + o1 + cl);
                p0.x *= c[mi][ni][0] * wa;
                p0.y *= c[mi][ni][1] * wa;
                p1.x *= c[mi][ni][2] * wb;
                p1.y *= c[mi][ni][3] * wb;
                *reinterpret_cast<float2*>(g_A + o0 + cl) = p0;
                *reinterpret_cast<float2*>(g_A + o1 + cl) = p1;
            }
        }
    } else {
        float* po = g_part + (size_t)z * (T_TOK * H_DIM);
#pragma unroll
        for (int mi = 0; mi < 2; mi++) {
            int r0 = r_base + mi * 16 + g;
            size_t o0 = (size_t)r0 * H_DIM;
            size_t o1 = (size_t)(r0 + 8) * H_DIM;
#pragma unroll
            for (int ni = 0; ni < 8; ni++) {
                int cl = c_base + ni * 8 + 2 * tg;
                float2 v0 = make_float2(c[mi][ni][0], c[mi][ni][1]);
                float2 v1 = make_float2(c[mi][ni][2], c[mi][ni][3]);
                *reinterpret_cast<float2*>(po + o0 + cl) = v0;
                *reinterpret_cast<float2*>(po + o1 + cl) = v1;
            }
        }
    }
}

// Sum the two K-split partials into the final output.
__global__ void add_kernel(float* __restrict__ out) {
    int i = (blockIdx.x * blockDim.x + threadIdx.x) * 4;
    float4 a = *reinterpret_cast<const float4*>(g_part + i);
    float4 b = *reinterpret_cast<const float4*>(g_part + (size_t)T_TOK * H_DIM + i);
    float4 r = make_float4(a.x + b.x, a.y + b.y, a.z + b.z, a.w + b.w);
    *reinterpret_cast<float4*>(out + i) = r;
}

extern "C" void kernel_launch(void* const* d_in, const int* in_sizes, int n_in,
                              void* d_out, int out_size) {
    const float* x  = (const float*)d_in[0];  // (1,1,T,H)
    const float* wg = (const float*)d_in[1];  // (H,E)
    const float* w1 = (const float*)d_in[2];  // (E,H,F)
    const float* w3 = (const float*)d_in[3];  // (E,H,F)
    const float* w2 = (const float*)d_in[4];  // (E,F,H) == (E*F, H) row-major
    float* out = (float*)d_out;               // (1,1,T,H)

    // 1) Gate weights
    gate_kernel<<<T_TOK / 8, 256>>>(x, wg);

    // 2) A' pass a: silu(x @ w1[e]) -> g_A
    dim3 g2(F_DIM / 128, T_TOK / 128, E_EXP);
    gemm_kernel<<<g2, 256>>>(x, w1, H_DIM, H_DIM, F_DIM, 0);

    // 3) A' pass b: g_A *= (x @ w3[e]) * weight[t,e]
    gemm_kernel<<<g2, 256>>>(x, w3, H_DIM, H_DIM, F_DIM, 1);

    // 4) out = A'(T x E*F) @ w2(E*F x H), K split in 2 slices for occupancy
    dim3 g3(H_DIM / 128, T_TOK / 128, 2);
    gemm_kernel<<<g3, 256>>>(nullptr, w2, (int)(EFDIM / 2), (int)EFDIM, H_DIM, 2);

    // 5) Reduce K-split partials
    add_kernel<<<(T_TOK * H_DIM) / (256 * 4), 256>>>(out);
}

// round 2
// speedup vs baseline: 1.9646x; 1.9646x over previous
#include <cuda_runtime.h>
#include <stdint.h>
#include <math.h>

#define T_TOK 1024
#define H_DIM 2048
#define F_DIM 4096
#define E_EXP 8
#define ROWS_CAP 3072
#define MTILES (ROWS_CAP / 128)   // 24

// ---------------- scratch (device globals; allocation-free) ----------------
__device__ int   g_cnt[E_EXP];
__device__ int   g_fill[E_EXP];
__device__ int   g_off[E_EXP + 1];
__device__ int   g_tile_e[MTILES];
__device__ int   g_rows[ROWS_CAP];          // row -> token
__device__ float g_rw[ROWS_CAP];            // row -> gate weight
__device__ int   g_pos[T_TOK * 2];          // (token,slot) -> row
__device__ int   g_te[T_TOK * 2];           // (token,slot) -> expert
__device__ float g_tw[T_TOK * 2];           // (token,slot) -> weight
__device__ float g_A[(size_t)ROWS_CAP * F_DIM];   // 50 MB
__device__ float g_Y[(size_t)ROWS_CAP * H_DIM];   // 25 MB

__device__ __forceinline__ uint32_t f2tf(float f) {
    uint32_t u;
    asm("cvt.rna.tf32.f32 %0, %1;" : "=r"(u) : "f"(f));
    return u;
}
__device__ __forceinline__ float silu_f(float v) { return v / (1.0f + expf(-v)); }

__device__ __forceinline__ void mma_tf32(float& c0, float& c1, float& c2, float& c3,
                                         uint32_t a0, uint32_t a1, uint32_t a2, uint32_t a3,
                                         uint32_t b0, uint32_t b1) {
    asm volatile(
        "mma.sync.aligned.m16n8k8.row.col.f32.tf32.tf32.f32 "
        "{%0,%1,%2,%3}, {%4,%5,%6,%7}, {%8,%9}, {%0,%1,%2,%3};\n"
        : "+f"(c0), "+f"(c1), "+f"(c2), "+f"(c3)
        : "r"(a0), "r"(a1), "r"(a2), "r"(a3), "r"(b0), "r"(b1));
}

// --------------------------- routing pipeline ------------------------------
__global__ void init_kernel() {
    if (threadIdx.x < E_EXP) g_cnt[threadIdx.x] = 0;
}

// one warp per token: logits -> top2 -> weights, counts
__global__ void gate_kernel(const float* __restrict__ x, const float* __restrict__ wg) {
    int t = blockIdx.x * (blockDim.x >> 5) + (threadIdx.x >> 5);
    int lane = threadIdx.x & 31;
    if (t >= T_TOK) return;

    const float* xr = x + (size_t)t * H_DIM;
    float acc[E_EXP];
#pragma unroll
    for (int e = 0; e < E_EXP; e++) acc[e] = 0.0f;
    for (int h = lane; h < H_DIM; h += 32) {
        float xv = xr[h];
        const float* wrow = wg + (size_t)h * E_EXP;
#pragma unroll
        for (int e = 0; e < E_EXP; e++) acc[e] += xv * wrow[e];
    }
#pragma unroll
    for (int e = 0; e < E_EXP; e++) {
#pragma unroll
        for (int o = 16; o > 0; o >>= 1) acc[e] += __shfl_xor_sync(0xffffffffu, acc[e], o);
    }
    if (lane == 0) {
        int i0 = 0; float v0 = acc[0];
#pragma unroll
        for (int e = 1; e < E_EXP; e++) if (acc[e] > v0) { v0 = acc[e]; i0 = e; }
        int i1 = -1; float v1 = -INFINITY;
#pragma unroll
        for (int e = 0; e < E_EXP; e++) if (e != i0 && acc[e] > v1) { v1 = acc[e]; i1 = e; }
        float w0 = 1.0f / (1.0f + expf(v1 - v0));
        g_te[2 * t] = i0;     g_tw[2 * t] = w0;
        g_te[2 * t + 1] = i1; g_tw[2 * t + 1] = 1.0f - w0;
        atomicAdd(&g_cnt[i0], 1);
        atomicAdd(&g_cnt[i1], 1);
    }
}

// single block: 128-aligned segment offsets, tile->expert map, init rows
__global__ void route_kernel() {
    __shared__ int soff[E_EXP + 1];
    if (threadIdx.x == 0) {
        int o = 0;
#pragma unroll
        for (int e = 0; e < E_EXP; e++) {
            soff[e] = o;
            o += (g_cnt[e] + 127) & ~127;
        }
        soff[E_EXP] = o;
#pragma unroll
        for (int e = 0; e <= E_EXP; e++) g_off[e] = soff[e];
#pragma unroll
        for (int e = 0; e < E_EXP; e++) g_fill[e] = 0;
    }
    __syncthreads();
    if (threadIdx.x < MTILES) {
        int i = threadIdx.x;
        int e = -1;
#pragma unroll
        for (int ee = 0; ee < E_EXP; ee++)
            if (i * 128 >= soff[ee] && i * 128 < soff[ee + 1]) e = ee;
        g_tile_e[i] = e;
    }
    for (int r = threadIdx.x; r < ROWS_CAP; r += blockDim.x) {
        g_rows[r] = 0;
        g_rw[r] = 0.0f;
    }
}

__global__ void scatter_kernel() {
    int t = blockIdx.x * blockDim.x + threadIdx.x;
    if (t >= T_TOK) return;
#pragma unroll
    for (int s = 0; s < 2; s++) {
        int e = g_te[2 * t + s];
        int r = g_off[e] + atomicAdd(&g_fill[e], 1);
        g_rows[r] = t;
        g_rw[r] = g_tw[2 * t + s];
        g_pos[2 * t + s] = r;
    }
}

// ---------------------------------------------------------------------------
// tf32 GEMM on permuted rows. 128x128x32 tile, 256 threads (4Mx2N warps),
// double-buffered smem + register prefetch (1 __syncthreads per K-tile).
//
// mode 0: C = x[rows] @ w1[e];  g_A[r, n] = silu(C)
// mode 1: C = x[rows] @ w3[e];  g_A[r, n] *= C * g_rw[r]
// mode 2: C = g_A @ w2[e];      g_Y[r, n] = C
// ---------------------------------------------------------------------------
#define AS_WORDS 4608   // 128 * 36
#define BS_WORDS 4224   // 32 * 132
#define SMEM_BYTES ((2 * AS_WORDS + 2 * BS_WORDS) * 4)

__global__ __launch_bounds__(256) void gemm_kernel(const float* __restrict__ X,
                                                   const float* __restrict__ W,
                                                   int K, int lda, int ldb, int mode) {
    extern __shared__ uint32_t smem[];
    uint32_t* As0 = smem;                       // [2][128][36]
    uint32_t* Bs0 = smem + 2 * AS_WORDS;        // [2][32][132]

    const int my = blockIdx.y;
    const int e = g_tile_e[my];
    if (e < 0) return;

    const int tid = threadIdx.x;
    const int warp = tid >> 5;
    const int lane = tid & 31;
    const int wm = warp & 3;
    const int wn = warp >> 2;
    const int g = lane >> 2;
    const int tg = lane & 3;

    const int bm = my * 128;
    const int bn = blockIdx.x * 128;

    const float* Bbase = W + (size_t)e * (size_t)K * (size_t)ldb;

    // per-thread staging sources (fixed rows, advance along K)
    const float* aptr[4];
    const float* bptr[4];
#pragma unroll
    for (int i = 0; i < 4; i++) {
        int slot = tid + i * 256;
        int r = slot >> 3;
        int c4 = (slot & 7) << 2;
        if (mode <= 1)
            aptr[i] = X + (size_t)g_rows[bm + r] * lda + c4;
        else
            aptr[i] = g_A + (size_t)(bm + r) * lda + c4;
    }
#pragma unroll
    for (int i = 0; i < 4; i++) {
        int slot = tid + i * 256;
        int r = slot >> 5;
        int c4 = (slot & 31) << 2;
        bptr[i] = Bbase + (size_t)r * ldb + bn + c4;
    }

    float c[2][8][4];
#pragma unroll
    for (int mi = 0; mi < 2; mi++)
#pragma unroll
        for (int ni = 0; ni < 8; ni++)
#pragma unroll
            for (int q = 0; q < 4; q++) c[mi][ni][q] = 0.0f;

    // preload first K-tile into registers
    float4 ra[4], rb[4];
#pragma unroll
    for (int i = 0; i < 4; i++) {
        ra[i] = *reinterpret_cast<const float4*>(aptr[i]);
        rb[i] = *reinterpret_cast<const float4*>(bptr[i]);
        aptr[i] += 32;
        bptr[i] += (size_t)32 * ldb;
    }

    int buf = 0;
    for (int k0 = 0; k0 < K; k0 += 32) {
        // store staged registers -> smem[buf]
        uint32_t* Asb = As0 + buf * AS_WORDS;
        uint32_t* Bsb = Bs0 + buf * BS_WORDS;
#pragma unroll
        for (int i = 0; i < 4; i++) {
            int slot = tid + i * 256;
            int r = slot >> 3;
            int c4 = (slot & 7) << 2;
            uint4 u = make_uint4(f2tf(ra[i].x), f2tf(ra[i].y), f2tf(ra[i].z), f2tf(ra[i].w));
            *reinterpret_cast<uint4*>(Asb + r * 36 + c4) = u;
        }
#pragma unroll
        for (int i = 0; i < 4; i++) {
            int slot = tid + i * 256;
            int r = slot >> 5;
            int c4 = (slot & 31) << 2;
            uint4 u = make_uint4(f2tf(rb[i].x), f2tf(rb[i].y), f2tf(rb[i].z), f2tf(rb[i].w));
            *reinterpret_cast<uint4*>(Bsb + r * 132 + c4) = u;
        }
        __syncthreads();

        // prefetch next K-tile while computing this one
        if (k0 + 32 < K) {
#pragma unroll
            for (int i = 0; i < 4; i++) {
                ra[i] = *reinterpret_cast<const float4*>(aptr[i]);
                rb[i] = *reinterpret_cast<const float4*>(bptr[i]);
                aptr[i] += 32;
                bptr[i] += (size_t)32 * ldb;
            }
        }

#pragma unroll
        for (int ks = 0; ks < 4; ks++) {
            const int kk = ks * 8;
            uint32_t a[2][4];
            uint32_t b[8][2];
#pragma unroll
            for (int mi = 0; mi < 2; mi++) {
                int r0 = wm * 32 + mi * 16;
                a[mi][0] = Asb[(r0 + g) * 36 + kk + tg];
                a[mi][1] = Asb[(r0 + 8 + g) * 36 + kk + tg];
                a[mi][2] = Asb[(r0 + g) * 36 + kk + tg + 4];
                a[mi][3] = Asb[(r0 + 8 + g) * 36 + kk + tg + 4];
            }
#pragma unroll
            for (int ni = 0; ni < 8; ni++) {
                int col = wn * 64 + ni * 8 + g;
                b[ni][0] = Bsb[(kk + tg) * 132 + col];
                b[ni][1] = Bsb[(kk + tg + 4) * 132 + col];
            }
#pragma unroll
            for (int mi = 0; mi < 2; mi++)
#pragma unroll
                for (int ni = 0; ni < 8; ni++)
                    mma_tf32(c[mi][ni][0], c[mi][ni][1], c[mi][ni][2], c[mi][ni][3],
                             a[mi][0], a[mi][1], a[mi][2], a[mi][3],
                             b[ni][0], b[ni][1]);
        }
        buf ^= 1;
        __syncthreads();
    }

    // epilogue; c0->(r0,cl), c1->(r0,cl+1), c2->(r0+8,cl), c3->(r0+8,cl+1)
    const int r_base = bm + wm * 32;
    const int c_base = bn + wn * 64;

    if (mode == 0) {
#pragma unroll
        for (int mi = 0; mi < 2; mi++) {
            int r0 = r_base + mi * 16 + g;
            size_t o0 = (size_t)r0 * F_DIM;
            size_t o1 = (size_t)(r0 + 8) * F_DIM;
#pragma unroll
            for (int ni = 0; ni < 8; ni++) {
                int cl = c_base + ni * 8 + 2 * tg;
                float2 v0 = make_float2(silu_f(c[mi][ni][0]), silu_f(c[mi][ni][1]));
                float2 v1 = make_float2(silu_f(c[mi][ni][2]), silu_f(c[mi][ni][3]));
                *reinterpret_cast<float2*>(g_A + o0 + cl) = v0;
                *reinterpret_cast<float2*>(g_A + o1 + cl) = v1;
            }
        }
    } else if (mode == 1) {
#pragma unroll
        for (int mi = 0; mi < 2; mi++) {
            int r0 = r_base + mi * 16 + g;
            float wa = g_rw[r0];
            float wb = g_rw[r0 + 8];
            size_t o0 = (size_t)r0 * F_DIM;
            size_t o1 = (size_t)(r0 + 8) * F_DIM;
#pragma unroll
            for (int ni = 0; ni < 8; ni++) {
                int cl = c_base + ni * 8 + 2 * tg;
                float2 p0 = *reinterpret_cast<const float2*>(g_A + o0 + cl);
                float2 p1 = *reinterpret_cast<const float2*>(g_A + o1 + cl);
                p0.x *= c[mi][ni][0] * wa;
                p0.y *= c[mi][ni][1] * wa;
                p1.x *= c[mi][ni][2] * wb;
                p1.y *= c[mi][ni][3] * wb;
                *reinterpret_cast<float2*>(g_A + o0 + cl) = p0;
                *reinterpret_cast<float2*>(g_A + o1 + cl) = p1;
            }
        }
    } else {
#pragma unroll
        for (int mi = 0; mi < 2; mi++) {
            int r0 = r_base + mi * 16 + g;
            size_t o0 = (size_t)r0 * H_DIM;
            size_t o1 = (size_t)(r0 + 8) * H_DIM;
#pragma unroll
            for (int ni = 0; ni < 8; ni++) {
                int cl = c_base + ni * 8 + 2 * tg;
                float2 v0 = make_float2(c[mi][ni][0], c[mi][ni][1]);
                float2 v1 = make_float2(c[mi][ni][2], c[mi][ni][3]);
                *reinterpret_cast<float2*>(g_Y + o0 + cl) = v0;
                *reinterpret_cast<float2*>(g_Y + o1 + cl) = v1;
            }
        }
    }
}

// out[t] = Y[pos(t,0)] + Y[pos(t,1)]  (weights already folded into g_A)
__global__ void combine_kernel(float* __restrict__ out) {
    int i = blockIdx.x * blockDim.x + threadIdx.x;  // one float4 per thread
    int t = i / (H_DIM / 4);
    int h = (i % (H_DIM / 4)) * 4;
    int r0 = g_pos[2 * t];
    int r1 = g_pos[2 * t + 1];
    float4 a = *reinterpret_cast<const float4*>(g_Y + (size_t)r0 * H_DIM + h);
    float4 b = *reinterpret_cast<const float4*>(g_Y + (size_t)r1 * H_DIM + h);
    float4 r = make_float4(a.x + b.x, a.y + b.y, a.z + b.z, a.w + b.w);
    *reinterpret_cast<float4*>(out + (size_t)t * H_DIM + h) = r;
}

extern "C" void kernel_launch(void* const* d_in, const int* in_sizes, int n_in,
                              void* d_out, int out_size) {
    const float* x  = (const float*)d_in[0];  // (1,1,T,H)
    const float* wg = (const float*)d_in[1];  // (H,E)
    const float* w1 = (const float*)d_in[2];  // (E,H,F)
    const float* w3 = (const float*)d_in[3];  // (E,H,F)
    const float* w2 = (const float*)d_in[4];  // (E,F,H)
    float* out = (float*)d_out;

    cudaFuncSetAttribute(gemm_kernel, cudaFuncAttributeMaxDynamicSharedMemorySize, SMEM_BYTES);

    init_kernel<<<1, 32>>>();
    gate_kernel<<<T_TOK / 8, 256>>>(x, wg);
    route_kernel<<<1, 256>>>();
    scatter_kernel<<<T_TOK / 256, 256>>>();

    dim3 g1(F_DIM / 128, MTILES);
    gemm_kernel<<<g1, 256, SMEM_BYTES>>>(x, w1, H_DIM, H_DIM, F_DIM, 0);
    gemm_kernel<<<g1, 256, SMEM_BYTES>>>(x, w3, H_DIM, H_DIM, F_DIM, 1);

    dim3 g2(H_DIM / 128, MTILES);
    gemm_kernel<<<g2, 256, SMEM_BYTES>>>(nullptr, w2, F_DIM, F_DIM, H_DIM, 2);

    combine_kernel<<<(T_TOK * H_DIM / 4) / 256, 256>>>(out);
}